// round 8
// baseline (speedup 1.0000x reference)
#include <cuda_runtime.h>
#include <cuda_fp16.h>

#define B        64
#define NV       100000
#define NE       (3 * NV)        // 300000 floats per batch row
#define NT       200000          // tets
#define VOL_BLOCKS 1184          // 8 blocks/SM * 148 SMs (one full wave)
#define E_TILE   64
#define T_TILES  ((NE + E_TILE - 1) / E_TILE)   // 4688 (last tile partial: 32)
#define P_BLOCKS ((NT + 255) / 256)             // 782 prep blocks

// Scratch (static device globals — no runtime allocation)
__device__ __half    g_xt[B * NE];               // transposed fp16: xt[e*64 + b]
__device__ int4      g_off4[NT];                 // {o0,o1,o2,pad}, o = idx*192
__device__ float     g_part[B * VOL_BLOCKS];     // partials, [b][blk] transposed
__device__ float     g_inv[B];                   // 1/cbrt(vol)
__device__ unsigned  g_count = 0;                // last-block counter (self-resetting)

// ---------------------------------------------------------------------------
// Kernel 0 (heterogeneous): blocks [0, T_TILES) transpose+convert x -> xt
// with 64e x 64b tiles (4 x LDG.128 per thread for MLP);
// blocks [T_TILES, ...) convert M -> fused int4 offsets.
// ---------------------------------------------------------------------------
__global__ void k_pt(const float* __restrict__ x, const void* __restrict__ Mv) {
    __shared__ float tile[E_TILE][65];
    const int tid = threadIdx.x;              // 256 threads

    if (blockIdx.x < T_TILES) {
        const int e0 = blockIdx.x * E_TILE;
        // load: 1024 tasks = 64 b x 16 float4-chunks along e
        #pragma unroll
        for (int k = 0; k < 4; k++) {
            int task = tid + k * 256;
            int b  = task >> 4;               // 0..63
            int c4 = task & 15;               // float4 chunk along e
            int e  = e0 + 4 * c4;
            if (e < NE) {
                float4 v = *(const float4*)(x + b * NE + e);
                tile[4 * c4 + 0][b] = v.x;
                tile[4 * c4 + 1][b] = v.y;
                tile[4 * c4 + 2][b] = v.z;
                tile[4 * c4 + 3][b] = v.w;
            }
        }
        __syncthreads();
        // store: 512 tasks = 64 e x 8 16B-chunks along b
        #pragma unroll
        for (int k = 0; k < 2; k++) {
            int task = tid + k * 256;
            int e = task >> 3;                // 0..63
            int c = task & 7;                 // 16B chunk along b (8 halves)
            if (e0 + e < NE) {
                __half2 h[4];
                #pragma unroll
                for (int j = 0; j < 4; j++)
                    h[j] = __floats2half2_rn(tile[e][8 * c + 2 * j],
                                             tile[e][8 * c + 2 * j + 1]);
                ((int4*)(g_xt + (e0 + e) * B))[c] = *(int4*)h;
            }
        }
    } else {
        // ---------------- index-prep path ----------------
        __shared__ int s_is64;
        if (tid == 0) {
            const int* Mi = (const int*)Mv;
            int nz = 0;
            #pragma unroll
            for (int k = 0; k < 32; k++) nz |= Mi[2 * k + 1];
            s_is64 = (nz == 0);
        }
        __syncthreads();
        int t = (blockIdx.x - T_TILES) * 256 + tid;
        if (t >= NT) return;
        int i0, i1, i2;
        if (s_is64) {
            const long long* Ml = (const long long*)Mv;
            i0 = (int)Ml[3 * t]; i1 = (int)Ml[3 * t + 1]; i2 = (int)Ml[3 * t + 2];
        } else {
            const int* Mi = (const int*)Mv;
            i0 = Mi[3 * t]; i1 = Mi[3 * t + 1]; i2 = Mi[3 * t + 2];
        }
        g_off4[t] = make_int4(i0 * (3 * B), i1 * (3 * B), i2 * (3 * B), 0);
    }
}

// ---------------------------------------------------------------------------
// Kernel 1: per-batch |det| partial sums + fused last-block reduce.
// Block = 256 threads = 32 lanes (half2 = 2 batches) x 8 tet-streams.
// det math in half2, fp32 accumulation. Also L2-prefetches x (2 lines/thread,
// interleaved) so the following k_scale reads hit L2 instead of DRAM.
// ---------------------------------------------------------------------------
__global__ void k_volume(const float* __restrict__ x) {
    const int tid  = threadIdx.x;
    const int lane = tid & 31;                // batch-pair id
    const int sub  = tid >> 5;                // tet stream 0..7

    // prefetch targets: x has exactly 600000 128B lines; 303104 threads
    const unsigned gid = blockIdx.x * 256u + tid;
    const float* pf0 = x + (size_t)gid * 32;
    const float* pf1 = x + ((size_t)gid + 303104u) * 32;

    float2 acc = make_float2(0.0f, 0.0f);
    const int stride = VOL_BLOCKS * 8;
    int j = 0;
    #pragma unroll 4
    for (int t = blockIdx.x * 8 + sub; t < NT; t += stride, j++) {
        if (j == 5)
            asm volatile("prefetch.global.L2 [%0];" :: "l"(pf0));
        if (j == 13 && gid < 296896u)
            asm volatile("prefetch.global.L2 [%0];" :: "l"(pf1));

        const int4 o = __ldg(&g_off4[t]);

        const __half2* p0 = (const __half2*)(g_xt + o.x) + lane;
        const __half2* p1 = (const __half2*)(g_xt + o.y) + lane;
        const __half2* p2 = (const __half2*)(g_xt + o.z) + lane;

        __half2 ax = p0[0], ay = p0[32], az = p0[64];
        __half2 bx = p1[0], by = p1[32], bz = p1[64];
        __half2 cx = p2[0], cy = p2[32], cz = p2[64];

        __half2 nbz = __hneg2(bz);
        __half2 m0 = __hfma2(by, cz, __hmul2(nbz, cy));         // by*cz - bz*cy
        __half2 m1 = __hfma2(bx, cz, __hmul2(nbz, cx));         // bx*cz - bz*cx
        __half2 m2 = __hfma2(bx, cy, __hmul2(__hneg2(by), cx)); // bx*cy - by*cx

        __half2 det = __hmul2(ax, m0);
        det = __hfma2(__hneg2(ay), m1, det);
        det = __hfma2(az, m2, det);
        det = __habs2(det);

        float2 f = __half22float2(det);
        acc.x += f.x;
        acc.y += f.y;
    }

    __shared__ float2 sred[8][32];
    sred[sub][lane] = acc;
    __syncthreads();
    if (sub == 0) {
        float2 s = acc;
        #pragma unroll
        for (int r = 1; r < 8; r++) {
            s.x += sred[r][lane].x;
            s.y += sred[r][lane].y;
        }
        g_part[(2 * lane + 0) * VOL_BLOCKS + blockIdx.x] = s.x;
        g_part[(2 * lane + 1) * VOL_BLOCKS + blockIdx.x] = s.y;
    }

    // ---- fused deterministic reduce in the last block to finish ----
    __shared__ int s_last;
    if (tid == 0) {
        __threadfence();
        unsigned c = atomicAdd(&g_count, 1u);
        s_last = (c == VOL_BLOCKS - 1);
    }
    __syncthreads();
    if (!s_last) return;

    {
        const int b = tid >> 2;               // 0..63
        const int q = tid & 3;                // 296-float contiguous chunk
        const float4* p = (const float4*)(g_part + b * VOL_BLOCKS + q * 296);
        float s = 0.0f;
        #pragma unroll 4
        for (int i = 0; i < 74; i++) {
            float4 v = p[i];
            s += (v.x + v.y) + (v.z + v.w);
        }
        __shared__ float sq[64][4];
        sq[b][q] = s;
        __syncthreads();
        if (tid < 64) {
            float vol = ((sq[tid][0] + sq[tid][1]) + (sq[tid][2] + sq[tid][3]))
                        * (1.0f / 6.0f);
            g_inv[tid] = 1.0f / cbrtf(vol);
        }
        if (tid == 0) g_count = 0;            // reset for next graph replay
    }
}

// ---------------------------------------------------------------------------
// Kernel 2: out = x * inv_scale[b]; streaming hints so the write stream
// doesn't evict prefetched x from L2 before it's read.
// ---------------------------------------------------------------------------
__global__ void k_scale(const float* __restrict__ x, float* __restrict__ out) {
    const int bb = blockIdx.y;
    const int n4 = NE / 4;                    // 75000
    const float s = __ldg(&g_inv[bb]);
    const float4* xi = (const float4*)(x + bb * NE);
    float4*       oo = (float4*)(out + bb * NE);

    const int step = 37 * 256;                // 9472
    for (int j4 = blockIdx.x * 256 + threadIdx.x; j4 < n4; j4 += step) {
        float4 v = __ldcs(&xi[j4]);
        v.x *= s; v.y *= s; v.z *= s; v.w *= s;
        __stcs(&oo[j4], v);
    }
}

// ---------------------------------------------------------------------------
extern "C" void kernel_launch(void* const* d_in, const int* in_sizes, int n_in,
                              void* d_out, int out_size) {
    const float* x = (const float*)d_in[0];
    const void*  M = d_in[1];
    float*     out = (float*)d_out;

    k_pt<<<T_TILES + P_BLOCKS, 256>>>(x, M);
    k_volume<<<VOL_BLOCKS, 256>>>(x);
    dim3 g(37, B);
    k_scale<<<g, 256>>>(x, out);
}